// round 1
// baseline (speedup 1.0000x reference)
#include <cuda_runtime.h>

#define D        256
#define TM       64
#define TN       64
#define SROW     260   // padded smem row stride (floats): breaks the stride-256 bank pattern
#define NMAX     8192

__device__ float g_esq[NMAX];

// ---------------------------------------------------------------------------
// Prepass: e_sq[n] = sum_d embed[n][d]^2.  One warp per code row.
// ---------------------------------------------------------------------------
__global__ void esq_kernel(const float* __restrict__ embed, int N) {
    int warp = (blockIdx.x * blockDim.x + threadIdx.x) >> 5;
    int lane = threadIdx.x & 31;
    if (warp >= N) return;
    const float4* row = (const float4*)(embed + (size_t)warp * D);
    float s = 0.f;
    #pragma unroll
    for (int i = lane; i < D / 4; i += 32) {
        float4 v = row[i];
        s += v.x * v.x + v.y * v.y + v.z * v.z + v.w * v.w;
    }
    #pragma unroll
    for (int o = 16; o; o >>= 1) s += __shfl_xor_sync(0xFFFFFFFFu, s, o);
    if (lane == 0) g_esq[warp] = s;
}

// ---------------------------------------------------------------------------
// Fused distance-GEMM + argmin + gather.
// CTA: 256 threads as 16x16; owns TM=64 rows of x. Streams embed in TN=64
// code tiles. Each thread computes a 4x4 micro-tile of dot products per tile,
// maintains running (best_val, best_idx) for its 4 rows, reduces across the
// 16 column-threads at the end, then gathers the winning code rows.
// ---------------------------------------------------------------------------
extern __shared__ float dyn_smem[];

__global__ __launch_bounds__(256) void vq_kernel(
    const float* __restrict__ x,
    const float* __restrict__ embed,
    float* __restrict__ out,
    int M, int N, long long out_size)
{
    float* xs = dyn_smem;                 // [TM][SROW]
    float* es = dyn_smem + TM * SROW;     // [TN][SROW]

    __shared__ float red_val[TM][16];
    __shared__ int   red_idx[TM][16];
    __shared__ int   best_row[TM];

    const int tid = threadIdx.x;
    const int tx = tid & 15;
    const int ty = tid >> 4;
    const int rowBase = blockIdx.x * TM;

    // Load x tile once: 64 rows x 64 float4
    for (int i = tid; i < TM * (D / 4); i += 256) {
        int r = i >> 6, kv = i & 63;
        float4 v = ((const float4*)(x + (size_t)(rowBase + r) * D))[kv];
        float* dst = &xs[r * SROW + kv * 4];
        dst[0] = v.x; dst[1] = v.y; dst[2] = v.z; dst[3] = v.w;
    }

    float bestv[4];
    int   besti[4];
    #pragma unroll
    for (int i = 0; i < 4; i++) { bestv[i] = 3.4e38f; besti[i] = 0; }

    for (int nt = 0; nt < N; nt += TN) {
        __syncthreads();   // protects es from previous iteration (and xs on iter 0)
        for (int i = tid; i < TN * (D / 4); i += 256) {
            int r = i >> 6, kv = i & 63;
            float4 v = ((const float4*)(embed + (size_t)(nt + r) * D))[kv];
            float* dst = &es[r * SROW + kv * 4];
            dst[0] = v.x; dst[1] = v.y; dst[2] = v.z; dst[3] = v.w;
        }
        __syncthreads();

        float acc[4][4];
        #pragma unroll
        for (int i = 0; i < 4; i++)
            #pragma unroll
            for (int j = 0; j < 4; j++) acc[i][j] = 0.f;

        const float* xp = &xs[(ty * 4) * SROW];
        const float* ep = &es[(tx * 4) * SROW];

        #pragma unroll 4
        for (int k = 0; k < D; k += 4) {
            float4 a[4], b[4];
            #pragma unroll
            for (int i = 0; i < 4; i++) a[i] = *(const float4*)(xp + i * SROW + k);
            #pragma unroll
            for (int j = 0; j < 4; j++) b[j] = *(const float4*)(ep + j * SROW + k);
            #pragma unroll
            for (int i = 0; i < 4; i++)
                #pragma unroll
                for (int j = 0; j < 4; j++) {
                    acc[i][j] += a[i].x * b[j].x;
                    acc[i][j] += a[i].y * b[j].y;
                    acc[i][j] += a[i].z * b[j].z;
                    acc[i][j] += a[i].w * b[j].w;
                }
        }

        float eq[4];
        #pragma unroll
        for (int j = 0; j < 4; j++) eq[j] = g_esq[nt + tx * 4 + j];

        #pragma unroll
        for (int i = 0; i < 4; i++)
            #pragma unroll
            for (int j = 0; j < 4; j++) {
                float score = eq[j] - 2.0f * acc[i][j];
                int   idx   = nt + tx * 4 + j;
                if (score < bestv[i]) { bestv[i] = score; besti[i] = idx; }
                // ascending j + strict < => lowest index wins ties within thread
            }
    }

    __syncthreads();
    #pragma unroll
    for (int i = 0; i < 4; i++) {
        red_val[ty * 4 + i][tx] = bestv[i];
        red_idx[ty * 4 + i][tx] = besti[i];
    }
    __syncthreads();

    if (tid < TM) {
        float bv = 3.4e38f;
        int   bi = 0x7FFFFFFF;
        #pragma unroll
        for (int t = 0; t < 16; t++) {
            float v  = red_val[tid][t];
            int   id = red_idx[tid][t];
            if (v < bv || (v == bv && id < bi)) { bv = v; bi = id; }
        }
        best_row[tid] = bi;
        long long iout = (long long)M * D + rowBase + tid;
        if (iout < out_size) out[iout] = (float)bi;   // index output as fp32
    }
    __syncthreads();

    // Gather: quantized[row] = embed[best_idx[row]]
    for (int i = tid; i < TM * (D / 4); i += 256) {
        int r = i >> 6, kv = i & 63;
        float4 v = ((const float4*)(embed + (size_t)best_row[r] * D))[kv];
        ((float4*)(out + (size_t)(rowBase + r) * D))[kv] = v;
    }
}

// ---------------------------------------------------------------------------
extern "C" void kernel_launch(void* const* d_in, const int* in_sizes, int n_in,
                              void* d_out, int out_size)
{
    const float* x     = (const float*)d_in[0];
    const float* embed = (const float*)d_in[1];
    float*       out   = (float*)d_out;

    int M = in_sizes[0] / D;   // 8192 rows of x
    int N = in_sizes[1] / D;   // 8192 codes
    if (N > NMAX) N = NMAX;

    // Prepass: ||e||^2 per code (one warp per code)
    int esq_blocks = (N * 32 + 255) / 256;
    esq_kernel<<<esq_blocks, 256>>>(embed, N);

    // Main fused kernel
    size_t smem = (size_t)(TM + TN) * SROW * sizeof(float);   // ~133 KB
    cudaFuncSetAttribute(vq_kernel, cudaFuncAttributeMaxDynamicSharedMemorySize,
                         (int)smem);
    vq_kernel<<<M / TM, 256, smem>>>(x, embed, out, M, N, (long long)out_size);
}

// round 2
// speedup vs baseline: 2.5901x; 2.5901x over previous
#include <cuda_runtime.h>

#define D        256
#define TM       64
#define TN       256
#define BK       32
#define NMAX     8192

__device__ float g_esq[NMAX];

// ---------------------------------------------------------------------------
// Prepass: e_sq[n] = sum_d embed[n][d]^2.  One warp per code row.
// ---------------------------------------------------------------------------
__global__ void esq_kernel(const float* __restrict__ embed, int N) {
    int warp = (blockIdx.x * blockDim.x + threadIdx.x) >> 5;
    int lane = threadIdx.x & 31;
    if (warp >= N) return;
    const float4* row = (const float4*)(embed + (size_t)warp * D);
    float s = 0.f;
    #pragma unroll
    for (int i = lane; i < D / 4; i += 32) {
        float4 v = row[i];
        s += v.x * v.x + v.y * v.y + v.z * v.z + v.w * v.w;
    }
    #pragma unroll
    for (int o = 16; o; o >>= 1) s += __shfl_xor_sync(0xFFFFFFFFu, s, o);
    if (lane == 0) g_esq[warp] = s;
}

// ---------------------------------------------------------------------------
// Fused distance-GEMM + argmin + gather, 8x8 microtile, K-major smem.
//
// CTA: 256 threads, tile TM=64 rows x TN=256 codes.
//   thread (tx=lane 0..31, ty=warp 0..7)
//   rows:  ty*4+i (i<4) and 32+ty*4+i   -> A loads are warp-broadcast
//   cols:  tx*4+j (j<4) and 128+tx*4+j  -> B loads are consecutive float4
// xs: x tile transposed [K=256][TM=64], resident (64 KB)
// es: embed chunk transposed [BK=32][TN=256], streamed (32 KB), reg-prefetched
// ---------------------------------------------------------------------------
extern __shared__ float dyn_smem[];

__global__ __launch_bounds__(256, 1) void vq_kernel(
    const float* __restrict__ x,
    const float* __restrict__ embed,
    float* __restrict__ out,
    int M, int N, long long out_size)
{
    float* xs = dyn_smem;              // [256][64]  k-major
    float* es = dyn_smem + D * TM;     // [BK][256]  k-major

    __shared__ int best_row[TM];

    const int tid  = threadIdx.x;
    const int lane = tid & 31;         // tx
    const int warp = tid >> 5;         // ty
    const int rowBase = blockIdx.x * TM;

    // ---- Load x tile transposed: thread t -> row (t&63), k-section (t>>6)
    {
        int r    = tid & 63;
        int ksec = tid >> 6;           // 0..3, each covers 16 float4 = 64 k
        const float4* src = (const float4*)(x + (size_t)(rowBase + r) * D);
        #pragma unroll
        for (int kv = ksec * 16; kv < ksec * 16 + 16; kv++) {
            float4 v = src[kv];
            xs[(kv * 4 + 0) * TM + r] = v.x;
            xs[(kv * 4 + 1) * TM + r] = v.y;
            xs[(kv * 4 + 2) * TM + r] = v.z;
            xs[(kv * 4 + 3) * TM + r] = v.w;
        }
    }

    float bestv[8];
    int   besti[8];
    #pragma unroll
    for (int i = 0; i < 8; i++) { bestv[i] = 3.4e38f; besti[i] = 0; }

    const int nChunksPerTile = D / BK;                 // 8
    const int nTiles         = N / TN;                 // 32
    const int totalChunks    = nTiles * nChunksPerTile;

    // ---- Prefetch chunk 0 (nt=0, kt=0): thread t owns es row t (8 float4)
    float4 pf[8];
    {
        const float4* p = (const float4*)(embed + (size_t)tid * D);
        #pragma unroll
        for (int q = 0; q < 8; q++) pf[q] = p[q];
    }

    int cid = 0;   // linear chunk id = tileIdx*8 + kt
    for (int nt = 0; nt < N; nt += TN) {
        float acc[8][8];
        #pragma unroll
        for (int i = 0; i < 8; i++)
            #pragma unroll
            for (int j = 0; j < 8; j++) acc[i][j] = 0.f;

        for (int kt = 0; kt < nChunksPerTile; kt++, cid++) {
            __syncthreads();                 // prior compute done reading es
            // store prefetched chunk, transposed: conflict-free (lane = row)
            #pragma unroll
            for (int q = 0; q < 8; q++) {
                es[(q * 4 + 0) * TN + tid] = pf[q].x;
                es[(q * 4 + 1) * TN + tid] = pf[q].y;
                es[(q * 4 + 2) * TN + tid] = pf[q].z;
                es[(q * 4 + 3) * TN + tid] = pf[q].w;
            }
            __syncthreads();

            // issue next chunk's LDGs before compute (hide gmem latency)
            int ncid = cid + 1;
            if (ncid < totalChunks) {
                int nnt = (ncid >> 3) * TN;
                int nkt = ncid & 7;
                const float4* p =
                    (const float4*)(embed + (size_t)(nnt + tid) * D) + nkt * 8;
                #pragma unroll
                for (int q = 0; q < 8; q++) pf[q] = p[q];
            }

            // compute this chunk
            const float* xk = xs + (size_t)kt * BK * TM;
            #pragma unroll 8
            for (int kk = 0; kk < BK; kk++) {
                float4 A0 = *(const float4*)(xk + kk * TM + warp * 4);
                float4 A1 = *(const float4*)(xk + kk * TM + 32 + warp * 4);
                float4 B0 = *(const float4*)(es + kk * TN + lane * 4);
                float4 B1 = *(const float4*)(es + kk * TN + 128 + lane * 4);
                float a_[8] = {A0.x, A0.y, A0.z, A0.w, A1.x, A1.y, A1.z, A1.w};
                float b_[8] = {B0.x, B0.y, B0.z, B0.w, B1.x, B1.y, B1.z, B1.w};
                #pragma unroll
                for (int i = 0; i < 8; i++)
                    #pragma unroll
                    for (int j = 0; j < 8; j++)
                        acc[i][j] += a_[i] * b_[j];
            }
        }

        // ---- epilogue: argmin update over this tile's 8 cols per thread
        float eq[8];
        #pragma unroll
        for (int j = 0; j < 4; j++) {
            eq[j]     = __ldg(&g_esq[nt + lane * 4 + j]);
            eq[j + 4] = __ldg(&g_esq[nt + 128 + lane * 4 + j]);
        }
        #pragma unroll
        for (int i = 0; i < 8; i++) {
            #pragma unroll
            for (int j = 0; j < 8; j++) {   // j ascending = col index ascending
                float score = eq[j] - 2.0f * acc[i][j];
                int   col = (j < 4) ? (nt + lane * 4 + j)
                                    : (nt + 128 + lane * 4 + (j - 4));
                if (score < bestv[i]) { bestv[i] = score; besti[i] = col; }
            }
        }
    }

    // ---- warp-shuffle argmin reduce across the 32 col-threads (tie: min idx)
    #pragma unroll
    for (int i = 0; i < 8; i++) {
        float v  = bestv[i];
        int   ix = besti[i];
        #pragma unroll
        for (int off = 16; off; off >>= 1) {
            float ov = __shfl_xor_sync(0xFFFFFFFFu, v, off);
            int   oi = __shfl_xor_sync(0xFFFFFFFFu, ix, off);
            if (ov < v || (ov == v && oi < ix)) { v = ov; ix = oi; }
        }
        if (lane == 0) {
            int row = (i < 4) ? (warp * 4 + i) : (32 + warp * 4 + (i - 4));
            best_row[row] = ix;
            out[(long long)M * D + rowBase + row] = (float)ix;  // index as fp32
        }
    }
    __syncthreads();

    // ---- gather: quantized[row] = embed[best_idx[row]]
    for (int i = tid; i < TM * (D / 4); i += 256) {
        int r = i >> 6, kv = i & 63;
        float4 v = ((const float4*)(embed + (size_t)best_row[r] * D))[kv];
        ((float4*)(out + (size_t)(rowBase + r) * D))[kv] = v;
    }
}

// ---------------------------------------------------------------------------
extern "C" void kernel_launch(void* const* d_in, const int* in_sizes, int n_in,
                              void* d_out, int out_size)
{
    const float* x     = (const float*)d_in[0];
    const float* embed = (const float*)d_in[1];
    float*       out   = (float*)d_out;

    int M = in_sizes[0] / D;   // 8192 rows of x
    int N = in_sizes[1] / D;   // 8192 codes
    if (N > NMAX) N = NMAX;

    int esq_blocks = (N * 32 + 255) / 256;
    esq_kernel<<<esq_blocks, 256>>>(embed, N);

    size_t smem = (size_t)(D * TM + BK * TN) * sizeof(float);   // 96 KB
    cudaFuncSetAttribute(vq_kernel, cudaFuncAttributeMaxDynamicSharedMemorySize,
                         (int)smem);
    vq_kernel<<<M / TM, 256, smem>>>(x, embed, out, M, N, (long long)out_size);
}